// round 1
// baseline (speedup 1.0000x reference)
#include <cuda_runtime.h>
#include <cuda_bf16.h>

// DifferentiableTopKSelector reduces exactly to: per-row hard top-K(=32) mask
// of raw scores. The straight-through estimator hard - sg(soft) + soft is
// value-identical to hard_mask up to <=1e-7 fp32 cancellation noise, and the
// Gumbel/softmax branch (and the `u` input) contribute nothing to the value.
//
// Per row (8192 fp32): MSB radix-select (4x8-bit passes, shared-mem histogram)
// finds the exact rank-32 key; ties broken lowest-index-first to match
// jax.lax.top_k's stable ordering.

static constexpr int COLS = 8192;
static constexpr int NT   = 256;
static constexpr int KSEL = 32;

__device__ __forceinline__ unsigned key_of(unsigned b) {
    // Order-preserving map fp32 bits -> uint32 (larger key == larger float)
    return (b & 0x80000000u) ? ~b : (b | 0x80000000u);
}

__global__ void __launch_bounds__(NT)
topk_mask_kernel(const float* __restrict__ scores, float* __restrict__ out) {
    __shared__ unsigned skey[COLS];        // 32 KB row of keys
    __shared__ unsigned hist[256];
    __shared__ unsigned s_digit, s_krem, s_eq;

    const int t = threadIdx.x;
    const size_t rowoff = (size_t)blockIdx.x * (size_t)COLS;
    const uint4* in4 = (const uint4*)(scores + rowoff);
    uint4* sk4 = (uint4*)skey;

    // ---- stage row into smem as monotone keys (coalesced 16B loads) ----
    for (int v = t; v < COLS / 4; v += NT) {
        uint4 b = in4[v];
        uint4 kk;
        kk.x = key_of(b.x);
        kk.y = key_of(b.y);
        kk.z = key_of(b.z);
        kk.w = key_of(b.w);
        sk4[v] = kk;
    }
    __syncthreads();

    // ---- 4-pass MSB radix select for the rank-KSEL key ----
    unsigned prefix = 0u, pmask = 0u, krem = KSEL;
    for (int shift = 24; shift >= 0; shift -= 8) {
        hist[t] = 0u;                       // NT == 256 bins
        __syncthreads();

        for (int v = t; v < COLS / 4; v += NT) {
            uint4 kk = sk4[v];
            unsigned ks[4] = {kk.x, kk.y, kk.z, kk.w};
            #pragma unroll
            for (int j = 0; j < 4; ++j) {
                if ((ks[j] & pmask) == prefix)
                    atomicAdd(&hist[(ks[j] >> shift) & 0xFFu], 1u);
            }
        }
        __syncthreads();

        if (t == 0) {
            unsigned cum = 0u;
            int b;
            for (b = 255; b >= 0; --b) {
                cum += hist[b];
                if (cum >= krem) break;
            }
            s_digit = (unsigned)b;
            s_krem  = krem - (cum - hist[b]);   // how many of digit-b elems to keep
            if (shift == 0) s_eq = hist[b];      // exact-key equal count E
        }
        __syncthreads();

        prefix |= s_digit << shift;
        pmask  |= 0xFFu << shift;
        krem    = s_krem;
        __syncthreads();
    }

    const unsigned T  = prefix;   // exact key of the rank-KSEL element
    const unsigned eq = s_eq;     // count of elements with key == T

    // ---- rare true-tie case: keep only the lowest-index krem equals ----
    // (matches jax.lax.top_k stable tie-break). Uniform branch; serial scan is
    // fine because P(tie at the rank boundary) ~ 2e-5 per row.
    if (eq != krem) {
        if (t == 0) {
            unsigned rem = krem;
            for (int i = 0; i < COLS; ++i) {
                if (skey[i] == T) {
                    if (rem) --rem;
                    else skey[i] = 0u;   // demote below T (T has MSB set, so 0 < T)
                }
            }
        }
        __syncthreads();
    }

    // ---- coalesced mask write ----
    float4* out4 = (float4*)(out + rowoff);
    for (int v = t; v < COLS / 4; v += NT) {
        uint4 kk = sk4[v];
        float4 o;
        o.x = (kk.x >= T) ? 1.0f : 0.0f;
        o.y = (kk.y >= T) ? 1.0f : 0.0f;
        o.z = (kk.z >= T) ? 1.0f : 0.0f;
        o.w = (kk.w >= T) ? 1.0f : 0.0f;
        out4[v] = o;
    }
}

extern "C" void kernel_launch(void* const* d_in, const int* in_sizes, int n_in,
                              void* d_out, int out_size) {
    const float* scores = (const float*)d_in[0];   // (4096, 8192) fp32
    // d_in[1] (u) is mathematically dead: output == hard top-k mask of scores.
    float* out = (float*)d_out;
    const int rows = out_size / COLS;              // 4096
    topk_mask_kernel<<<rows, NT>>>(scores, out);
}

// round 2
// speedup vs baseline: 3.1631x; 3.1631x over previous
#include <cuda_runtime.h>
#include <cuda_bf16.h>

// DifferentiableTopKSelector == per-row hard top-32 mask of raw scores
// (straight-through estimator is value-identical to hard_mask; `u` is dead).
//
// Strategy: single streaming pass over the row. Write zeros to the output
// inline (it must be fully written anyway), and gather the few elements
// above a fixed guess threshold G=2.0 into a small smem candidate list
// (~186 of 8192 for N(0,1) rows). Then compute the exact stable rank of
// each candidate by all-pairs comparison (ties broken lowest-index-first,
// matching jax.lax.top_k), and scatter 1.0f at the 32 winners.
//
// Exactness guard: if the candidate count is < 32 (guess too high) or
// overflows the buffer, thread 0 runs a serial exact stable top-32.
// Never taken for this dataset (mean count 186, sigma 13.5 -> 11-sigma
// margin on both sides), but keeps the kernel correct for any input.

static constexpr int COLS = 8192;
static constexpr int NT   = 256;
static constexpr int VPT  = COLS / 4 / NT;   // 8 float4 per thread
static constexpr int CAP  = 2048;            // candidate buffer capacity
static constexpr int KSEL = 32;
#define GUESS 2.0f

__global__ void __launch_bounds__(NT)
topk_mask_kernel(const float* __restrict__ scores, float* __restrict__ out) {
    __shared__ uint2 cand[CAP];    // (float bits, index) — 16 KB
    __shared__ int   s_cnt;

    const int t = threadIdx.x;
    if (t == 0) s_cnt = 0;
    __syncthreads();

    const size_t rowoff = (size_t)blockIdx.x * (size_t)COLS;
    const float4* in4  = (const float4*)(scores + rowoff);
    float4*       out4 = (float4*)(out + rowoff);
    const float4  zero4 = make_float4(0.f, 0.f, 0.f, 0.f);

    // ---- one streaming pass: read row, write zeros, gather candidates ----
    #pragma unroll
    for (int it = 0; it < VPT; ++it) {
        const int v = t + it * NT;
        float4 val = in4[v];
        out4[v] = zero4;
        float a[4] = {val.x, val.y, val.z, val.w};
        #pragma unroll
        for (int j = 0; j < 4; ++j) {
            if (a[j] > GUESS) {
                int slot = atomicAdd(&s_cnt, 1);
                if (slot < CAP)
                    cand[slot] = make_uint2(__float_as_uint(a[j]),
                                            (unsigned)(v * 4 + j));
            }
        }
    }
    __syncthreads();

    const int cnt = s_cnt;

    if (cnt >= KSEL && cnt <= CAP) {
        // ---- exact stable rank among candidates (all positive floats:
        //      uint compare on the bits == float compare) ----
        for (int i = t; i < cnt; i += NT) {
            const uint2 ci = cand[i];
            int r = 0;
            for (int j = 0; j < cnt; ++j) {
                const uint2 cj = cand[j];            // LDS broadcast
                r += (cj.x > ci.x) | ((cj.x == ci.x) & (cj.y < ci.y));
            }
            if (r < KSEL)
                out[rowoff + ci.y] = 1.0f;
        }
    } else if (t == 0) {
        // ---- exact serial fallback (never taken for N(0,1) rows) ----
        float    bk[KSEL];
        unsigned bi[KSEL];
        #pragma unroll
        for (int i = 0; i < KSEL; ++i) { bk[i] = -INFINITY; bi[i] = 0u; }
        const float* rowp = scores + rowoff;
        for (int i = 0; i < COLS; ++i) {
            float vv = rowp[i];
            // strict > keeps earlier (lower-index) equal keys: stable top-k
            if (vv > bk[KSEL - 1]) {
                int p = KSEL - 1;
                while (p > 0 && vv > bk[p - 1]) {
                    bk[p] = bk[p - 1]; bi[p] = bi[p - 1]; --p;
                }
                bk[p] = vv; bi[p] = (unsigned)i;
            }
        }
        for (int i = 0; i < KSEL; ++i)
            out[rowoff + bi[i]] = 1.0f;
    }
}

extern "C" void kernel_launch(void* const* d_in, const int* in_sizes, int n_in,
                              void* d_out, int out_size) {
    const float* scores = (const float*)d_in[0];   // (4096, 8192) fp32
    // d_in[1] (u) is mathematically dead: output == hard top-k mask of scores.
    float* out = (float*)d_out;
    const int rows = out_size / COLS;              // 4096
    topk_mask_kernel<<<rows, NT>>>(scores, out);
}

// round 3
// speedup vs baseline: 5.7591x; 1.8207x over previous
#include <cuda_runtime.h>
#include <cuda_bf16.h>

// DifferentiableTopKSelector == per-row hard top-32 mask of raw scores
// (straight-through estimator is value-identical to hard_mask; `u` is dead).
//
// One streaming pass: read row, write zeros, gather the ~88 elements above
// GUESS=2.3 as 64-bit composite keys (value bits << 32 | inverted index) into
// a tiny smem buffer. Exact stable rank via all-pairs u64 compare (composite
// key encodes jax.lax.top_k's lowest-index-first tie-break); scatter 1.0f at
// the 32 winners. Serial exact fallback if the guess misfires (6-sigma event).

static constexpr int COLS = 8192;
static constexpr int NT   = 256;
static constexpr int VPT  = COLS / 4 / NT;   // 8 float4 per thread
static constexpr int CAP  = 256;             // candidate buffer capacity
static constexpr int KSEL = 32;
#define GUESS 2.3f

__device__ __forceinline__ unsigned long long pack_key(float v, unsigned idx) {
    // v > GUESS > 0, so float bits compare as unsigned ints.
    // Inverted index: larger composite == (larger value, then smaller index).
    return ((unsigned long long)__float_as_uint(v) << 32)
         | (unsigned long long)(COLS - 1u - idx);
}

__global__ void __launch_bounds__(NT)
topk_mask_kernel(const float* __restrict__ scores, float* __restrict__ out) {
    __shared__ unsigned long long cand[CAP];   // 2 KB
    __shared__ int s_cnt;

    const int t = threadIdx.x;
    if (t == 0) s_cnt = 0;
    __syncthreads();

    const size_t rowoff = (size_t)blockIdx.x * (size_t)COLS;
    const float4* in4  = (const float4*)(scores + rowoff);
    float4*       out4 = (float4*)(out + rowoff);
    const float4  zero4 = make_float4(0.f, 0.f, 0.f, 0.f);

    // ---- one streaming pass: read row, write zeros, gather candidates ----
    #pragma unroll
    for (int it = 0; it < VPT; ++it) {
        const int v = t + it * NT;
        float4 val = in4[v];
        out4[v] = zero4;
        // single compare on the common path
        if (fmaxf(fmaxf(val.x, val.y), fmaxf(val.z, val.w)) > GUESS) {
            unsigned long long loc[4];
            int n = 0;
            const unsigned base = (unsigned)(v * 4);
            if (val.x > GUESS) loc[n++] = pack_key(val.x, base + 0u);
            if (val.y > GUESS) loc[n++] = pack_key(val.y, base + 1u);
            if (val.z > GUESS) loc[n++] = pack_key(val.z, base + 2u);
            if (val.w > GUESS) loc[n++] = pack_key(val.w, base + 3u);
            int slot = atomicAdd(&s_cnt, n);          // one atomic per hit-vec
            for (int q = 0; q < n; ++q)
                if (slot + q < CAP) cand[slot + q] = loc[q];
        }
    }
    __syncthreads();

    const int cnt = s_cnt;

    if (cnt >= KSEL && cnt <= CAP) {
        // ---- exact stable rank: all-pairs on composite keys ----
        for (int i = t; i < cnt; i += NT) {          // only warps with t < cnt run
            const unsigned long long ci = cand[i];
            int r = 0;
            #pragma unroll 4
            for (int j = 0; j < cnt; ++j)
                r += (cand[j] > ci);                 // LDS.64 broadcast
            if (r < KSEL) {
                unsigned idx = COLS - 1u - (unsigned)(ci & 0xFFFFFFFFull);
                out[rowoff + idx] = 1.0f;
            }
        }
    } else if (t == 0) {
        // ---- exact serial fallback (6-sigma event; correctness guard) ----
        float    bk[KSEL];
        unsigned bi[KSEL];
        #pragma unroll
        for (int i = 0; i < KSEL; ++i) { bk[i] = -INFINITY; bi[i] = 0u; }
        const float* rowp = scores + rowoff;
        for (int i = 0; i < COLS; ++i) {
            float vv = rowp[i];
            if (vv > bk[KSEL - 1]) {                 // strict > == stable
                int p = KSEL - 1;
                while (p > 0 && vv > bk[p - 1]) {
                    bk[p] = bk[p - 1]; bi[p] = bi[p - 1]; --p;
                }
                bk[p] = vv; bi[p] = (unsigned)i;
            }
        }
        for (int i = 0; i < KSEL; ++i)
            out[rowoff + bi[i]] = 1.0f;
    }
}

extern "C" void kernel_launch(void* const* d_in, const int* in_sizes, int n_in,
                              void* d_out, int out_size) {
    const float* scores = (const float*)d_in[0];   // (4096, 8192) fp32
    // d_in[1] (u) is mathematically dead: output == hard top-k mask of scores.
    float* out = (float*)d_out;
    const int rows = out_size / COLS;              // 4096
    topk_mask_kernel<<<rows, NT>>>(scores, out);
}

// round 4
// speedup vs baseline: 6.2816x; 1.0907x over previous
#include <cuda_runtime.h>
#include <cuda_bf16.h>

// DifferentiableTopKSelector == per-row hard top-32 mask of raw scores
// (straight-through estimator is value-identical to hard_mask; `u` is dead).
//
// Round 4: front-batch all 8 row loads (MLP_p1=8) before the zero stores and
// the candidate test, so DRAM latency is overlapped instead of exposed.
// Streaming cache hints (__ldcs/__stcs) since every byte is single-use.
// Candidates above GUESS=2.3 (~88/row for N(0,1)) go to a tiny smem list as
// 64-bit composite keys (value bits | inverted index); exact stable rank via
// all-pairs u64 compare matches jax.lax.top_k tie-breaking. Serial exact
// fallback guards any guess misfire (6-sigma event for this data).

static constexpr int COLS = 8192;
static constexpr int NT   = 256;
static constexpr int VPT  = COLS / 4 / NT;   // 8 float4 per thread
static constexpr int CAP  = 256;             // candidate buffer capacity
static constexpr int KSEL = 32;
#define GUESS 2.3f

__device__ __forceinline__ unsigned long long pack_key(float v, unsigned idx) {
    // v > GUESS > 0, so float bits compare as unsigned ints.
    // Inverted index: larger composite == (larger value, then smaller index).
    return ((unsigned long long)__float_as_uint(v) << 32)
         | (unsigned long long)(COLS - 1u - idx);
}

__device__ __forceinline__ float vmax4(float4 v) {
    return fmaxf(fmaxf(v.x, v.y), fmaxf(v.z, v.w));
}

__global__ void __launch_bounds__(NT)
topk_mask_kernel(const float* __restrict__ scores, float* __restrict__ out) {
    __shared__ unsigned long long cand[CAP];   // 2 KB
    __shared__ int s_cnt;

    const int t = threadIdx.x;
    if (t == 0) s_cnt = 0;
    __syncthreads();

    const size_t rowoff = (size_t)blockIdx.x * (size_t)COLS;
    const float4* in4  = (const float4*)(scores + rowoff);
    float4*       out4 = (float4*)(out + rowoff);
    const float4  zero4 = make_float4(0.f, 0.f, 0.f, 0.f);

    // ---- phase 1: all 8 loads issued back-to-back (MLP_p1 = 8) ----
    float4 v[VPT];
    #pragma unroll
    for (int it = 0; it < VPT; ++it)
        v[it] = __ldcs(in4 + t + it * NT);

    // ---- phase 2: zero fill (independent of loads; streams out early) ----
    #pragma unroll
    for (int it = 0; it < VPT; ++it)
        __stcs(out4 + t + it * NT, zero4);

    // ---- phase 3: candidate detection on registers ----
    float mx = vmax4(v[0]);
    #pragma unroll
    for (int it = 1; it < VPT; ++it)
        mx = fmaxf(mx, vmax4(v[it]));

    if (mx > GUESS) {                      // ~29% of threads; cold-ish path
        #pragma unroll
        for (int it = 0; it < VPT; ++it) {
            if (vmax4(v[it]) > GUESS) {
                unsigned long long loc[4];
                int n = 0;
                const unsigned base = (unsigned)((t + it * NT) * 4);
                if (v[it].x > GUESS) loc[n++] = pack_key(v[it].x, base + 0u);
                if (v[it].y > GUESS) loc[n++] = pack_key(v[it].y, base + 1u);
                if (v[it].z > GUESS) loc[n++] = pack_key(v[it].z, base + 2u);
                if (v[it].w > GUESS) loc[n++] = pack_key(v[it].w, base + 3u);
                int slot = atomicAdd(&s_cnt, n);
                for (int q = 0; q < n; ++q)
                    if (slot + q < CAP) cand[slot + q] = loc[q];
            }
        }
    }
    __syncthreads();

    const int cnt = s_cnt;

    if (cnt >= KSEL && cnt <= CAP) {
        // ---- exact stable rank: all-pairs on composite keys ----
        for (int i = t; i < cnt; i += NT) {          // only warps with t < cnt
            const unsigned long long ci = cand[i];
            int r = 0;
            #pragma unroll 4
            for (int j = 0; j < cnt; ++j)
                r += (cand[j] > ci);                 // LDS.64 broadcast
            if (r < KSEL) {
                unsigned idx = COLS - 1u - (unsigned)(ci & 0xFFFFFFFFull);
                out[rowoff + idx] = 1.0f;
            }
        }
    } else if (t == 0) {
        // ---- exact serial fallback (correctness guard; never taken here) ----
        float    bk[KSEL];
        unsigned bi[KSEL];
        #pragma unroll
        for (int i = 0; i < KSEL; ++i) { bk[i] = -INFINITY; bi[i] = 0u; }
        const float* rowp = scores + rowoff;
        for (int i = 0; i < COLS; ++i) {
            float vv = rowp[i];
            if (vv > bk[KSEL - 1]) {                 // strict > == stable
                int p = KSEL - 1;
                while (p > 0 && vv > bk[p - 1]) {
                    bk[p] = bk[p - 1]; bi[p] = bi[p - 1]; --p;
                }
                bk[p] = vv; bi[p] = (unsigned)i;
            }
        }
        for (int i = 0; i < KSEL; ++i)
            out[rowoff + bi[i]] = 1.0f;
    }
}

extern "C" void kernel_launch(void* const* d_in, const int* in_sizes, int n_in,
                              void* d_out, int out_size) {
    const float* scores = (const float*)d_in[0];   // (4096, 8192) fp32
    // d_in[1] (u) is mathematically dead: output == hard top-k mask of scores.
    float* out = (float*)d_out;
    const int rows = out_size / COLS;              // 4096
    topk_mask_kernel<<<rows, NT>>>(scores, out);
}